// round 14
// baseline (speedup 1.0000x reference)
#include <cuda_runtime.h>
#include <cstdint>
#include <cmath>

#define NCCOM 100000
#define NTOP  5000
#define NCLM  20000
#define HD 128
#define ESIM 600000
#define EAB  300000
#define ETG  300000
#define ETOT (ESIM+EAB+ETG)
#define NROWS3 (3*NCCOM)
#define SCAN_B 512
#define SCAN_NB ((NROWS3 + SCAN_B - 1) / SCAN_B)

// ---------------- device scratch ----------------
static __device__ float g_y1L[(size_t)NCCOM * 128];   // Wl products (gather input), compact
static __device__ float g_y1R[(size_t)NCCOM * 128];   // Wr_sum products (self term), compact
static __device__ float g_h1[(size_t)NCCOM * 128];    // h1
static __device__ float g_ytL1[(size_t)NTOP * 128];
static __device__ float g_ytL2[(size_t)NTOP * 128];
static __device__ float g_ycL1[(size_t)NCLM * 128];
static __device__ float g_ycL2[(size_t)NCLM * 128];
static __device__ int   g_src[ETOT];
static __device__ int   g_dst[ETOT];
static __device__ int   g_deg[NROWS3];
static __device__ int   g_rowptr[NROWS3 + 1];
static __device__ int   g_cursor[NROWS3];
static __device__ int   g_csr[ETOT];
static __device__ int   g_bsum[SCAN_NB];
static __device__ int   g_boff[SCAN_NB];
static __device__ float g_W1[256 * 256];               // [K=256][N=256]: [c1s_Wl | sum Wr]
static __device__ float g_W2[128 * 256];               // layer2 comment
static __device__ float g_Wtc[128 * 256];              // topic  [c1a_Wl | c2a_Wl]
static __device__ float g_Wcc[128 * 256];              // claim  [c1t_Wl | c2t_Wl]
static __device__ float g_Wh[12 * 128];
static __device__ float g_b1[128];
static __device__ float g_b2[128];
static __device__ int   g_is64;

// ---------------- packed f32x2 helpers ----------------
__device__ __forceinline__ void ffma2(unsigned long long& d, unsigned long long a,
                                      unsigned long long b) {
    asm("fma.rn.f32x2 %0, %1, %2, %0;" : "+l"(d) : "l"(a), "l"(b));
}
__device__ __forceinline__ unsigned long long rep2(float x) {
    unsigned long long r;
    asm("mov.b64 %0, {%1, %1};" : "=l"(r) : "f"(x));
    return r;
}
__device__ __forceinline__ void unpack2(unsigned long long v, float& lo, float& hi) {
    asm("mov.b64 {%0, %1}, %2;" : "=f"(lo), "=f"(hi) : "l"(v));
}

// ---------------- edge prep ----------------
__global__ void detect_kernel(const int* __restrict__ raw) {
    int allz = 1;
    for (int i = 0; i < 32; i++)
        if (raw[2 * i + 1] != 0) { allz = 0; break; }
    g_is64 = allz;
}

__global__ void convert_count(const int* __restrict__ raw, int* __restrict__ src,
                              int* __restrict__ dst, int* __restrict__ deg,
                              int E, int degbase) {
    int e = blockIdx.x * blockDim.x + threadIdx.x;
    if (e >= E) return;
    int s, d;
    if (g_is64) { s = raw[2 * (size_t)e]; d = raw[2 * ((size_t)E + e)]; }
    else        { s = raw[e];             d = raw[(size_t)E + e]; }
    src[e] = s;
    dst[e] = d;
    atomicAdd(&deg[degbase + d], 1);
}

__global__ void zero_kernel(float* __restrict__ p, size_t n4) {
    size_t stride = (size_t)gridDim.x * blockDim.x;
    for (size_t i = blockIdx.x * (size_t)blockDim.x + threadIdx.x; i < n4; i += stride)
        ((float4*)p)[i] = make_float4(0.f, 0.f, 0.f, 0.f);
}

__global__ void scan_bsum(const int* __restrict__ deg, int* __restrict__ bsum, int n) {
    __shared__ int sm[SCAN_B];
    int i = blockIdx.x * SCAN_B + threadIdx.x;
    sm[threadIdx.x] = (i < n) ? deg[i] : 0;
    __syncthreads();
    for (int o = SCAN_B / 2; o > 0; o >>= 1) {
        if (threadIdx.x < o) sm[threadIdx.x] += sm[threadIdx.x + o];
        __syncthreads();
    }
    if (threadIdx.x == 0) bsum[blockIdx.x] = sm[0];
}

__global__ void scan_offsets(const int* __restrict__ bsum, int* __restrict__ boff, int nb) {
    int acc = 0;
    for (int b = 0; b < nb; b++) { boff[b] = acc; acc += bsum[b]; }
}

__global__ void scan_write(const int* __restrict__ deg, const int* __restrict__ boff,
                           int* __restrict__ rowptr, int* __restrict__ cursor, int n) {
    __shared__ int sm[SCAN_B];
    int i = blockIdx.x * SCAN_B + threadIdx.x;
    int v = (i < n) ? deg[i] : 0;
    sm[threadIdx.x] = v;
    __syncthreads();
    for (int o = 1; o < SCAN_B; o <<= 1) {
        int t = (threadIdx.x >= o) ? sm[threadIdx.x - o] : 0;
        __syncthreads();
        sm[threadIdx.x] += t;
        __syncthreads();
    }
    if (i < n) {
        int ex = boff[blockIdx.x] + sm[threadIdx.x] - v;
        rowptr[i] = ex;
        cursor[i] = ex;
        if (i == n - 1) rowptr[n] = boff[blockIdx.x] + sm[threadIdx.x];
    }
}

__global__ void fill_csr(const int* __restrict__ src, const int* __restrict__ dst,
                         int* __restrict__ cursor, int* __restrict__ csr, int E, int degbase) {
    int e = blockIdx.x * blockDim.x + threadIdx.x;
    if (e >= E) return;
    int pos = atomicAdd(&cursor[degbase + dst[e]], 1);
    csr[pos] = src[e];
}

// ---------------- combined weight construction ----------------
__global__ void build_weights(
    const float* __restrict__ c1sWl, const float* __restrict__ c1sWr,
    const float* __restrict__ c1aWr, const float* __restrict__ c1tWr,
    const float* __restrict__ c2sWl, const float* __restrict__ c2sWr,
    const float* __restrict__ c2aWr, const float* __restrict__ c2tWr,
    const float* __restrict__ c1aWl, const float* __restrict__ c2aWl,
    const float* __restrict__ c1tWl, const float* __restrict__ c2tWl,
    const float* __restrict__ b1s, const float* __restrict__ b1a, const float* __restrict__ b1t,
    const float* __restrict__ b2s, const float* __restrict__ b2a, const float* __restrict__ b2t,
    const float* __restrict__ Wt, const float* __restrict__ Wi, const float* __restrict__ Wm)
{
    int i = blockIdx.x * blockDim.x + threadIdx.x;
    if (i < 65536) {                      // W1 [256 k][256 n]
        int k = i >> 8, j = i & 255;
        g_W1[i] = (j < 128) ? c1sWl[k * 128 + j]
                            : (c1sWr[k * 128 + j - 128] + c1aWr[k * 128 + j - 128] + c1tWr[k * 128 + j - 128]);
    } else if (i < 98304) {               // W2 [128 k][256 n]
        int t = i - 65536; int k = t >> 8, j = t & 255;
        g_W2[t] = (j < 128) ? c2sWl[k * 128 + j]
                            : (c2sWr[k * 128 + j - 128] + c2aWr[k * 128 + j - 128] + c2tWr[k * 128 + j - 128]);
    } else if (i < 131072) {              // Wtc [128 k][256 n]
        int t = i - 98304; int k = t >> 8, j = t & 255;
        g_Wtc[t] = (j < 128) ? c1aWl[k * 128 + j] : c2aWl[k * 128 + j - 128];
    } else if (i < 163840) {              // Wcc [128 k][256 n]
        int t = i - 131072; int k = t >> 8, j = t & 255;
        g_Wcc[t] = (j < 128) ? c1tWl[k * 128 + j] : c2tWl[k * 128 + j - 128];
    } else if (i < 164096) {
        int t = i - 163840;
        if (t < 128) g_b1[t] = b1s[t] + b1a[t] + b1t[t];
        else { int u = t - 128; g_b2[u] = b2s[u] + b2a[u] + b2t[u]; }
    } else if (i < 164096 + 1536) {
        int t = i - 164096;
        int j = t >> 7, k = t & 127;
        float v;
        if (j < 5) v = Wt[k * 5 + j];
        else if (j < 9) v = Wi[k * 4 + (j - 5)];
        else v = Wm[k * 3 + (j - 9)];
        g_Wh[t] = v;
    }
}

// ------- FFMA2 GEMM, split outputs: CL = A@B[:, 0:128], CR = A@B[:, 128:256] -------
// BM=128, BN=128 (per blockIdx.y half), BK=16, TM=8, TN=8, 256 threads.
template <int KTOT>
__global__ void __launch_bounds__(256, 2)
gemm_x2(const float* __restrict__ A, const float* __restrict__ B,
        float* __restrict__ CL, float* __restrict__ CR, int M)
{
    constexpr int BK = 16;
    __shared__ float As[BK][128 + 4];
    __shared__ float Bs[BK][128];
    const int tid = threadIdx.x;
    const int tx = tid & 15;
    const int ty = tid >> 4;
    const int bm0 = blockIdx.x * 128;
    const int bn0 = blockIdx.y * 128;
    float* __restrict__ C = (blockIdx.y == 0) ? CL : CR;

    unsigned long long acc[4][8];
#pragma unroll
    for (int i = 0; i < 4; i++)
#pragma unroll
        for (int j = 0; j < 8; j++) acc[i][j] = 0ull;

    for (int k0 = 0; k0 < KTOT; k0 += BK) {
#pragma unroll
        for (int f = tid; f < 128 * BK / 4; f += 256) {
            int row = f / (BK / 4);
            int k4 = f % (BK / 4);
            float4 v = make_float4(0.f, 0.f, 0.f, 0.f);
            if (bm0 + row < M)
                v = *(const float4*)(A + (size_t)(bm0 + row) * KTOT + k0 + k4 * 4);
            As[k4 * 4 + 0][row] = v.x;
            As[k4 * 4 + 1][row] = v.y;
            As[k4 * 4 + 2][row] = v.z;
            As[k4 * 4 + 3][row] = v.w;
        }
#pragma unroll
        for (int f = tid; f < BK * 128 / 4; f += 256) {
            int kr = f / 32;
            int c4 = f % 32;
            *(float4*)&Bs[kr][c4 * 4] = *(const float4*)(B + (size_t)(k0 + kr) * 256 + bn0 + c4 * 4);
        }
        __syncthreads();
#pragma unroll
        for (int kk = 0; kk < BK; kk++) {
            const float* ar = &As[kk][ty * 8];
            unsigned long long a0 = *(const unsigned long long*)(ar + 0);
            unsigned long long a1 = *(const unsigned long long*)(ar + 2);
            unsigned long long a2 = *(const unsigned long long*)(ar + 4);
            unsigned long long a3 = *(const unsigned long long*)(ar + 6);
            float4 bl = *(const float4*)&Bs[kk][tx * 8];
            float4 bh = *(const float4*)&Bs[kk][tx * 8 + 4];
            unsigned long long rb[8];
            rb[0] = rep2(bl.x); rb[1] = rep2(bl.y); rb[2] = rep2(bl.z); rb[3] = rep2(bl.w);
            rb[4] = rep2(bh.x); rb[5] = rep2(bh.y); rb[6] = rep2(bh.z); rb[7] = rep2(bh.w);
#pragma unroll
            for (int j = 0; j < 8; j++) {
                ffma2(acc[0][j], a0, rb[j]);
                ffma2(acc[1][j], a1, rb[j]);
                ffma2(acc[2][j], a2, rb[j]);
                ffma2(acc[3][j], a3, rb[j]);
            }
        }
        __syncthreads();
    }
#pragma unroll
    for (int i2 = 0; i2 < 4; i2++) {
        float lo[8], hi[8];
#pragma unroll
        for (int j = 0; j < 8; j++) unpack2(acc[i2][j], lo[j], hi[j]);
        int r0 = bm0 + ty * 8 + 2 * i2;
        if (r0 < M) {
            float* cp = C + (size_t)r0 * 128 + tx * 8;
            *(float4*)cp = make_float4(lo[0], lo[1], lo[2], lo[3]);
            *(float4*)(cp + 4) = make_float4(lo[4], lo[5], lo[6], lo[7]);
        }
        if (r0 + 1 < M) {
            float* cp = C + (size_t)(r0 + 1) * 128 + tx * 8;
            *(float4*)cp = make_float4(hi[0], hi[1], hi[2], hi[3]);
            *(float4*)(cp + 4) = make_float4(hi[4], hi[5], hi[6], hi[7]);
        }
    }
}

// ---------------- gather-aggregate (+ fused combine / heads), compact ld=128 ----------------
template <bool HEADS>
__global__ void gather_kernel(
    const float* __restrict__ yS, const float* __restrict__ yA, const float* __restrict__ yT,
    const int* __restrict__ rowptr, const int* __restrict__ csr,
    const float* __restrict__ selfp, const float* __restrict__ bias,
    float* __restrict__ out,
    const float* __restrict__ Wh, const float* __restrict__ Wm,
    const float* __restrict__ bt, const float* __restrict__ bi, const float* __restrict__ bm)
{
    int g = blockIdx.x * blockDim.x + threadIdx.x;
    int r = g >> 5;
    if (r >= NCCOM) return;
    int lane = g & 31;
    int c4 = lane * 4;

    float4 acc = make_float4(0.f, 0.f, 0.f, 0.f);
    const float* ys[3] = {yS, yA, yT};
#pragma unroll
    for (int t = 0; t < 3; t++) {
        int s0 = __ldg(rowptr + t * NCCOM + r);
        int s1 = __ldg(rowptr + t * NCCOM + r + 1);
        float4 l0 = make_float4(0.f, 0.f, 0.f, 0.f);
        float4 l1 = make_float4(0.f, 0.f, 0.f, 0.f);
        int e = s0;
        for (; e + 2 <= s1; e += 2) {
            int sa = __ldg(csr + e);
            int sb = __ldg(csr + e + 1);
            float4 va = *(const float4*)(ys[t] + (size_t)sa * 128 + c4);
            float4 vb = *(const float4*)(ys[t] + (size_t)sb * 128 + c4);
            l0.x += va.x; l0.y += va.y; l0.z += va.z; l0.w += va.w;
            l1.x += vb.x; l1.y += vb.y; l1.z += vb.z; l1.w += vb.w;
        }
        if (e < s1) {
            int sa = __ldg(csr + e);
            float4 va = *(const float4*)(ys[t] + (size_t)sa * 128 + c4);
            l0.x += va.x; l0.y += va.y; l0.z += va.z; l0.w += va.w;
        }
        float inv = 1.f / fmaxf((float)(s1 - s0), 1.f);
        acc.x += (l0.x + l1.x) * inv; acc.y += (l0.y + l1.y) * inv;
        acc.z += (l0.z + l1.z) * inv; acc.w += (l0.w + l1.w) * inv;
    }
    float4 sv = *(const float4*)(selfp + (size_t)r * 128 + c4);
    float4 bv = *(const float4*)(bias + c4);
    float h0 = fmaxf(acc.x + sv.x + bv.x, 0.f);
    float h1 = fmaxf(acc.y + sv.y + bv.y, 0.f);
    float h2 = fmaxf(acc.z + sv.z + bv.z, 0.f);
    float h3 = fmaxf(acc.w + sv.w + bv.w, 0.f);

    if (!HEADS) {
        *(float4*)(out + (size_t)r * HD + c4) = make_float4(h0, h1, h2, h3);
        return;
    }

    float a12[12];
#pragma unroll
    for (int j = 0; j < 12; j++) {
        float4 w = *(const float4*)(Wh + j * 128 + c4);
        a12[j] = h0 * w.x + h1 * w.y + h2 * w.z + h3 * w.w;
    }
#pragma unroll
    for (int o = 16; o > 0; o >>= 1)
#pragma unroll
        for (int j = 0; j < 12; j++) a12[j] += __shfl_xor_sync(0xffffffffu, a12[j], o);

    if (lane == 0) {
        float tl[5], tp[5], il[4], ip[4];
#pragma unroll
        for (int j = 0; j < 5; j++) { tl[j] = a12[j] + bt[j]; tp[j] = 1.f / (1.f + expf(-tl[j])); }
        float mx = -1e30f;
#pragma unroll
        for (int j = 0; j < 4; j++) { il[j] = a12[5 + j] + bi[j]; mx = fmaxf(mx, il[j]); }
        float se = 0.f;
#pragma unroll
        for (int j = 0; j < 4; j++) { ip[j] = expf(il[j] - mx); se += ip[j]; }
        float inv = 1.f / se;
#pragma unroll
        for (int j = 0; j < 4; j++) ip[j] *= inv;
        float* outT = out;
        float* outI = out + (size_t)NCCOM * 5;
        float* outM = out + (size_t)NCCOM * 9;
#pragma unroll
        for (int j = 0; j < 5; j++) outT[(size_t)r * 5 + j] = tl[j];
#pragma unroll
        for (int j = 0; j < 4; j++) outI[(size_t)r * 4 + j] = il[j];
#pragma unroll
        for (int j = 0; j < 3; j++) {
            float v = a12[9 + j] + bm[j];
#pragma unroll
            for (int t = 0; t < 5; t++) v += tp[t] * __ldg(Wm + (128 + t) * 3 + j);
#pragma unroll
            for (int t = 0; t < 4; t++) v += ip[t] * __ldg(Wm + (133 + t) * 3 + j);
            outM[(size_t)r * 3 + j] = v;
        }
    }
}

// ================= host launcher =================
extern "C" void kernel_launch(void* const* d_in, const int* in_sizes, int n_in,
                              void* d_out, int out_size)
{
    const float* x_c  = (const float*)d_in[0];
    const float* x_t  = (const float*)d_in[1];
    const float* x_cl = (const float*)d_in[2];
    const float* c1sWl = (const float*)d_in[3];
    const float* c1sbl = (const float*)d_in[4];
    const float* c1sWr = (const float*)d_in[5];
    const float* c1aWl = (const float*)d_in[6];
    const float* c1abl = (const float*)d_in[7];
    const float* c1aWr = (const float*)d_in[8];
    const float* c1tWl = (const float*)d_in[9];
    const float* c1tbl = (const float*)d_in[10];
    const float* c1tWr = (const float*)d_in[11];
    const float* c2sWl = (const float*)d_in[12];
    const float* c2sbl = (const float*)d_in[13];
    const float* c2sWr = (const float*)d_in[14];
    const float* c2aWl = (const float*)d_in[15];
    const float* c2abl = (const float*)d_in[16];
    const float* c2aWr = (const float*)d_in[17];
    const float* c2tWl = (const float*)d_in[18];
    const float* c2tbl = (const float*)d_in[19];
    const float* c2tWr = (const float*)d_in[20];
    const float* Wt = (const float*)d_in[21];
    const float* bt = (const float*)d_in[22];
    const float* Wi = (const float*)d_in[23];
    const float* bi = (const float*)d_in[24];
    const float* Wm = (const float*)d_in[25];
    const float* bm = (const float*)d_in[26];
    const int* ei_sim = (const int*)d_in[27];
    const int* ei_ab  = (const int*)d_in[28];
    const int* ei_tg  = (const int*)d_in[29];

    float *y1L, *y1R, *h1, *ytL1, *ytL2, *ycL1, *ycL2;
    int *src, *dst, *deg, *rowptr, *cursor, *csr, *bsum, *boff;
    float *W1, *W2, *Wtc, *Wcc, *Wh, *b1, *b2;
    cudaGetSymbolAddress((void**)&y1L, g_y1L);
    cudaGetSymbolAddress((void**)&y1R, g_y1R);
    cudaGetSymbolAddress((void**)&h1, g_h1);
    cudaGetSymbolAddress((void**)&ytL1, g_ytL1);
    cudaGetSymbolAddress((void**)&ytL2, g_ytL2);
    cudaGetSymbolAddress((void**)&ycL1, g_ycL1);
    cudaGetSymbolAddress((void**)&ycL2, g_ycL2);
    cudaGetSymbolAddress((void**)&src, g_src);
    cudaGetSymbolAddress((void**)&dst, g_dst);
    cudaGetSymbolAddress((void**)&deg, g_deg);
    cudaGetSymbolAddress((void**)&rowptr, g_rowptr);
    cudaGetSymbolAddress((void**)&cursor, g_cursor);
    cudaGetSymbolAddress((void**)&csr, g_csr);
    cudaGetSymbolAddress((void**)&bsum, g_bsum);
    cudaGetSymbolAddress((void**)&boff, g_boff);
    cudaGetSymbolAddress((void**)&W1, g_W1);
    cudaGetSymbolAddress((void**)&W2, g_W2);
    cudaGetSymbolAddress((void**)&Wtc, g_Wtc);
    cudaGetSymbolAddress((void**)&Wcc, g_Wcc);
    cudaGetSymbolAddress((void**)&Wh, g_Wh);
    cudaGetSymbolAddress((void**)&b1, g_b1);
    cudaGetSymbolAddress((void**)&b2, g_b2);

    int* srcS = src;              int* dstS = dst;
    int* srcA = src + ESIM;       int* dstA = dst + ESIM;
    int* srcT = src + ESIM + EAB; int* dstT = dst + ESIM + EAB;

    // Launch order arranged so the big GEMM is the 6th launch (ncu -s 5 -c 1).
    detect_kernel<<<1, 1>>>(ei_sim);                                    // 1
    zero_kernel<<<512, 256>>>((float*)deg, NROWS3 / 4);                 // 2
    build_weights<<<(165632 + 255) / 256, 256>>>(                        // 3
        c1sWl, c1sWr, c1aWr, c1tWr, c2sWl, c2sWr, c2aWr, c2tWr,
        c1aWl, c2aWl, c1tWl, c2tWl, c1sbl, c1abl, c1tbl, c2sbl, c2abl, c2tbl,
        Wt, Wi, Wm);
    convert_count<<<(ESIM + 255) / 256, 256>>>(ei_sim, srcS, dstS, deg, ESIM, 0);        // 4
    convert_count<<<(EAB + 255) / 256, 256>>>(ei_ab, srcA, dstA, deg, EAB, NCCOM);       // 5
    gemm_x2<256><<<dim3((NCCOM + 127) / 128, 2), 256>>>(x_c, W1, y1L, y1R, NCCOM);       // 6 <- ncu
    convert_count<<<(ETG + 255) / 256, 256>>>(ei_tg, srcT, dstT, deg, ETG, 2 * NCCOM);   // 7

    // CSR build
    scan_bsum<<<SCAN_NB, SCAN_B>>>(deg, bsum, NROWS3);
    scan_offsets<<<1, 1>>>(bsum, boff, SCAN_NB);
    scan_write<<<SCAN_NB, SCAN_B>>>(deg, boff, rowptr, cursor, NROWS3);
    fill_csr<<<(ESIM + 255) / 256, 256>>>(srcS, dstS, cursor, csr, ESIM, 0);
    fill_csr<<<(EAB + 255) / 256, 256>>>(srcA, dstA, cursor, csr, EAB, NCCOM);
    fill_csr<<<(ETG + 255) / 256, 256>>>(srcT, dstT, cursor, csr, ETG, 2 * NCCOM);

    // small GEMMs (topic/claim, both layers at once)
    gemm_x2<128><<<dim3((NTOP + 127) / 128, 2), 256>>>(x_t, Wtc, ytL1, ytL2, NTOP);
    gemm_x2<128><<<dim3((NCLM + 127) / 128, 2), 256>>>(x_cl, Wcc, ycL1, ycL2, NCLM);

    // layer-1 gather + combine
    gather_kernel<false><<<(NCCOM * 32 + 255) / 256, 256>>>(
        y1L, ytL1, ycL1, rowptr, csr, y1R, b1, h1,
        nullptr, nullptr, nullptr, nullptr, nullptr);

    // layer-2 GEMM (reuses y1L/y1R buffers) + gather + fused heads
    gemm_x2<128><<<dim3((NCCOM + 127) / 128, 2), 256>>>(h1, W2, y1L, y1R, NCCOM);
    gather_kernel<true><<<(NCCOM * 32 + 255) / 256, 256>>>(
        y1L, ytL2, ycL2, rowptr, csr, y1R, b2, (float*)d_out,
        Wh, Wm, bt, bi, bm);
}

// round 15
// speedup vs baseline: 1.0060x; 1.0060x over previous
#include <cuda_runtime.h>
#include <cstdint>
#include <cmath>

#define NCCOM 100000
#define NTOP  5000
#define NCLM  20000
#define HD 128
#define ESIM 600000
#define EAB  300000
#define ETG  300000
#define ETOT (ESIM+EAB+ETG)
#define NROWS3 (3*NCCOM)
#define SCAN_B 512
#define SCAN_NB ((NROWS3 + SCAN_B - 1) / SCAN_B)

// ---------------- device scratch ----------------
static __device__ float g_y1L[(size_t)NCCOM * 128];   // Wl products (gather input), compact
static __device__ float g_y1R[(size_t)NCCOM * 128];   // Wr_sum products (self term), compact
static __device__ float g_h1[(size_t)NCCOM * 128];    // h1
static __device__ float g_ytL1[(size_t)NTOP * 128];
static __device__ float g_ytL2[(size_t)NTOP * 128];
static __device__ float g_ycL1[(size_t)NCLM * 128];
static __device__ float g_ycL2[(size_t)NCLM * 128];
static __device__ int   g_src[ETOT];
static __device__ int   g_dst[ETOT];
static __device__ int   g_deg[NROWS3];
static __device__ int   g_rowptr[NROWS3 + 1];
static __device__ int   g_cursor[NROWS3];
static __device__ int   g_csr[ETOT];
static __device__ int   g_bsum[SCAN_NB];
static __device__ int   g_boff[SCAN_NB];
static __device__ float g_W1[256 * 256];               // [K=256][N=256]: [c1s_Wl | sum Wr]
static __device__ float g_W2[128 * 256];               // layer2 comment
static __device__ float g_Wtc[128 * 256];              // topic  [c1a_Wl | c2a_Wl]
static __device__ float g_Wcc[128 * 256];              // claim  [c1t_Wl | c2t_Wl]
static __device__ float g_Wh[12 * 128];
static __device__ float g_b1[128];
static __device__ float g_b2[128];
static __device__ int   g_is64;

// ---------------- packed f32x2 helpers ----------------
__device__ __forceinline__ void ffma2(unsigned long long& d, unsigned long long a,
                                      unsigned long long b) {
    asm("fma.rn.f32x2 %0, %1, %2, %0;" : "+l"(d) : "l"(a), "l"(b));
}
__device__ __forceinline__ unsigned long long rep2(float x) {
    unsigned long long r;
    asm("mov.b64 %0, {%1, %1};" : "=l"(r) : "f"(x));
    return r;
}
__device__ __forceinline__ void unpack2(unsigned long long v, float& lo, float& hi) {
    asm("mov.b64 {%0, %1}, %2;" : "=f"(lo), "=f"(hi) : "l"(v));
}

// ---------------- edge prep ----------------
__global__ void detect_kernel(const int* __restrict__ raw) {
    int allz = 1;
    for (int i = 0; i < 32; i++)
        if (raw[2 * i + 1] != 0) { allz = 0; break; }
    g_is64 = allz;
}

__global__ void convert_count(const int* __restrict__ raw, int* __restrict__ src,
                              int* __restrict__ dst, int* __restrict__ deg,
                              int E, int degbase) {
    int e = blockIdx.x * blockDim.x + threadIdx.x;
    if (e >= E) return;
    int s, d;
    if (g_is64) { s = raw[2 * (size_t)e]; d = raw[2 * ((size_t)E + e)]; }
    else        { s = raw[e];             d = raw[(size_t)E + e]; }
    src[e] = s;
    dst[e] = d;
    atomicAdd(&deg[degbase + d], 1);
}

__global__ void zero_kernel(float* __restrict__ p, size_t n4) {
    size_t stride = (size_t)gridDim.x * blockDim.x;
    for (size_t i = blockIdx.x * (size_t)blockDim.x + threadIdx.x; i < n4; i += stride)
        ((float4*)p)[i] = make_float4(0.f, 0.f, 0.f, 0.f);
}

__global__ void scan_bsum(const int* __restrict__ deg, int* __restrict__ bsum, int n) {
    __shared__ int sm[SCAN_B];
    int i = blockIdx.x * SCAN_B + threadIdx.x;
    sm[threadIdx.x] = (i < n) ? deg[i] : 0;
    __syncthreads();
    for (int o = SCAN_B / 2; o > 0; o >>= 1) {
        if (threadIdx.x < o) sm[threadIdx.x] += sm[threadIdx.x + o];
        __syncthreads();
    }
    if (threadIdx.x == 0) bsum[blockIdx.x] = sm[0];
}

__global__ void scan_offsets(const int* __restrict__ bsum, int* __restrict__ boff, int nb) {
    int acc = 0;
    for (int b = 0; b < nb; b++) { boff[b] = acc; acc += bsum[b]; }
}

__global__ void scan_write(const int* __restrict__ deg, const int* __restrict__ boff,
                           int* __restrict__ rowptr, int* __restrict__ cursor, int n) {
    __shared__ int sm[SCAN_B];
    int i = blockIdx.x * SCAN_B + threadIdx.x;
    int v = (i < n) ? deg[i] : 0;
    sm[threadIdx.x] = v;
    __syncthreads();
    for (int o = 1; o < SCAN_B; o <<= 1) {
        int t = (threadIdx.x >= o) ? sm[threadIdx.x - o] : 0;
        __syncthreads();
        sm[threadIdx.x] += t;
        __syncthreads();
    }
    if (i < n) {
        int ex = boff[blockIdx.x] + sm[threadIdx.x] - v;
        rowptr[i] = ex;
        cursor[i] = ex;
        if (i == n - 1) rowptr[n] = boff[blockIdx.x] + sm[threadIdx.x];
    }
}

__global__ void fill_csr(const int* __restrict__ src, const int* __restrict__ dst,
                         int* __restrict__ cursor, int* __restrict__ csr, int E, int degbase) {
    int e = blockIdx.x * blockDim.x + threadIdx.x;
    if (e >= E) return;
    int pos = atomicAdd(&cursor[degbase + dst[e]], 1);
    csr[pos] = src[e];
}

// ---------------- combined weight construction ----------------
__global__ void build_weights(
    const float* __restrict__ c1sWl, const float* __restrict__ c1sWr,
    const float* __restrict__ c1aWr, const float* __restrict__ c1tWr,
    const float* __restrict__ c2sWl, const float* __restrict__ c2sWr,
    const float* __restrict__ c2aWr, const float* __restrict__ c2tWr,
    const float* __restrict__ c1aWl, const float* __restrict__ c2aWl,
    const float* __restrict__ c1tWl, const float* __restrict__ c2tWl,
    const float* __restrict__ b1s, const float* __restrict__ b1a, const float* __restrict__ b1t,
    const float* __restrict__ b2s, const float* __restrict__ b2a, const float* __restrict__ b2t,
    const float* __restrict__ Wt, const float* __restrict__ Wi, const float* __restrict__ Wm)
{
    int i = blockIdx.x * blockDim.x + threadIdx.x;
    if (i < 65536) {                      // W1 [256 k][256 n]
        int k = i >> 8, j = i & 255;
        g_W1[i] = (j < 128) ? c1sWl[k * 128 + j]
                            : (c1sWr[k * 128 + j - 128] + c1aWr[k * 128 + j - 128] + c1tWr[k * 128 + j - 128]);
    } else if (i < 98304) {               // W2 [128 k][256 n]
        int t = i - 65536; int k = t >> 8, j = t & 255;
        g_W2[t] = (j < 128) ? c2sWl[k * 128 + j]
                            : (c2sWr[k * 128 + j - 128] + c2aWr[k * 128 + j - 128] + c2tWr[k * 128 + j - 128]);
    } else if (i < 131072) {              // Wtc [128 k][256 n]
        int t = i - 98304; int k = t >> 8, j = t & 255;
        g_Wtc[t] = (j < 128) ? c1aWl[k * 128 + j] : c2aWl[k * 128 + j - 128];
    } else if (i < 163840) {              // Wcc [128 k][256 n]
        int t = i - 131072; int k = t >> 8, j = t & 255;
        g_Wcc[t] = (j < 128) ? c1tWl[k * 128 + j] : c2tWl[k * 128 + j - 128];
    } else if (i < 164096) {
        int t = i - 163840;
        if (t < 128) g_b1[t] = b1s[t] + b1a[t] + b1t[t];
        else { int u = t - 128; g_b2[u] = b2s[u] + b2a[u] + b2t[u]; }
    } else if (i < 164096 + 1536) {
        int t = i - 164096;
        int j = t >> 7, k = t & 127;
        float v;
        if (j < 5) v = Wt[k * 5 + j];
        else if (j < 9) v = Wi[k * 4 + (j - 5)];
        else v = Wm[k * 3 + (j - 9)];
        g_Wh[t] = v;
    }
}

// ------- FFMA2 GEMM, split outputs: CL = A@B[:, 0:128], CR = A@B[:, 128:256] -------
// BM=128, BN=128 (per blockIdx.y half), BK=16, TM=8, TN=8, 256 threads.
template <int KTOT>
__global__ void __launch_bounds__(256, 2)
gemm_x2(const float* __restrict__ A, const float* __restrict__ B,
        float* __restrict__ CL, float* __restrict__ CR, int M)
{
    constexpr int BK = 16;
    __shared__ float As[BK][128 + 4];
    __shared__ float Bs[BK][128];
    const int tid = threadIdx.x;
    const int tx = tid & 15;
    const int ty = tid >> 4;
    const int bm0 = blockIdx.x * 128;
    const int bn0 = blockIdx.y * 128;
    float* __restrict__ C = (blockIdx.y == 0) ? CL : CR;

    unsigned long long acc[4][8];
#pragma unroll
    for (int i = 0; i < 4; i++)
#pragma unroll
        for (int j = 0; j < 8; j++) acc[i][j] = 0ull;

    for (int k0 = 0; k0 < KTOT; k0 += BK) {
#pragma unroll
        for (int f = tid; f < 128 * BK / 4; f += 256) {
            int row = f / (BK / 4);
            int k4 = f % (BK / 4);
            float4 v = make_float4(0.f, 0.f, 0.f, 0.f);
            if (bm0 + row < M)
                v = *(const float4*)(A + (size_t)(bm0 + row) * KTOT + k0 + k4 * 4);
            As[k4 * 4 + 0][row] = v.x;
            As[k4 * 4 + 1][row] = v.y;
            As[k4 * 4 + 2][row] = v.z;
            As[k4 * 4 + 3][row] = v.w;
        }
#pragma unroll
        for (int f = tid; f < BK * 128 / 4; f += 256) {
            int kr = f / 32;
            int c4 = f % 32;
            *(float4*)&Bs[kr][c4 * 4] = *(const float4*)(B + (size_t)(k0 + kr) * 256 + bn0 + c4 * 4);
        }
        __syncthreads();
#pragma unroll
        for (int kk = 0; kk < BK; kk++) {
            const float* ar = &As[kk][ty * 8];
            unsigned long long a0 = *(const unsigned long long*)(ar + 0);
            unsigned long long a1 = *(const unsigned long long*)(ar + 2);
            unsigned long long a2 = *(const unsigned long long*)(ar + 4);
            unsigned long long a3 = *(const unsigned long long*)(ar + 6);
            float4 bl = *(const float4*)&Bs[kk][tx * 8];
            float4 bh = *(const float4*)&Bs[kk][tx * 8 + 4];
            unsigned long long rb[8];
            rb[0] = rep2(bl.x); rb[1] = rep2(bl.y); rb[2] = rep2(bl.z); rb[3] = rep2(bl.w);
            rb[4] = rep2(bh.x); rb[5] = rep2(bh.y); rb[6] = rep2(bh.z); rb[7] = rep2(bh.w);
#pragma unroll
            for (int j = 0; j < 8; j++) {
                ffma2(acc[0][j], a0, rb[j]);
                ffma2(acc[1][j], a1, rb[j]);
                ffma2(acc[2][j], a2, rb[j]);
                ffma2(acc[3][j], a3, rb[j]);
            }
        }
        __syncthreads();
    }
#pragma unroll
    for (int i2 = 0; i2 < 4; i2++) {
        float lo[8], hi[8];
#pragma unroll
        for (int j = 0; j < 8; j++) unpack2(acc[i2][j], lo[j], hi[j]);
        int r0 = bm0 + ty * 8 + 2 * i2;
        if (r0 < M) {
            float* cp = C + (size_t)r0 * 128 + tx * 8;
            *(float4*)cp = make_float4(lo[0], lo[1], lo[2], lo[3]);
            *(float4*)(cp + 4) = make_float4(lo[4], lo[5], lo[6], lo[7]);
        }
        if (r0 + 1 < M) {
            float* cp = C + (size_t)(r0 + 1) * 128 + tx * 8;
            *(float4*)cp = make_float4(hi[0], hi[1], hi[2], hi[3]);
            *(float4*)(cp + 4) = make_float4(hi[4], hi[5], hi[6], hi[7]);
        }
    }
}

// ---------------- gather-aggregate (+ fused combine / heads), compact ld=128 ----------------
template <bool HEADS>
__global__ void gather_kernel(
    const float* __restrict__ yS, const float* __restrict__ yA, const float* __restrict__ yT,
    const int* __restrict__ rowptr, const int* __restrict__ csr,
    const float* __restrict__ selfp, const float* __restrict__ bias,
    float* __restrict__ out,
    const float* __restrict__ Wh, const float* __restrict__ Wm,
    const float* __restrict__ bt, const float* __restrict__ bi, const float* __restrict__ bm)
{
    int g = blockIdx.x * blockDim.x + threadIdx.x;
    int r = g >> 5;
    if (r >= NCCOM) return;
    int lane = g & 31;
    int c4 = lane * 4;

    float4 acc = make_float4(0.f, 0.f, 0.f, 0.f);
    const float* ys[3] = {yS, yA, yT};
#pragma unroll
    for (int t = 0; t < 3; t++) {
        int s0 = __ldg(rowptr + t * NCCOM + r);
        int s1 = __ldg(rowptr + t * NCCOM + r + 1);
        float4 l0 = make_float4(0.f, 0.f, 0.f, 0.f);
        float4 l1 = make_float4(0.f, 0.f, 0.f, 0.f);
        int e = s0;
        for (; e + 2 <= s1; e += 2) {
            int sa = __ldg(csr + e);
            int sb = __ldg(csr + e + 1);
            float4 va = *(const float4*)(ys[t] + (size_t)sa * 128 + c4);
            float4 vb = *(const float4*)(ys[t] + (size_t)sb * 128 + c4);
            l0.x += va.x; l0.y += va.y; l0.z += va.z; l0.w += va.w;
            l1.x += vb.x; l1.y += vb.y; l1.z += vb.z; l1.w += vb.w;
        }
        if (e < s1) {
            int sa = __ldg(csr + e);
            float4 va = *(const float4*)(ys[t] + (size_t)sa * 128 + c4);
            l0.x += va.x; l0.y += va.y; l0.z += va.z; l0.w += va.w;
        }
        float inv = 1.f / fmaxf((float)(s1 - s0), 1.f);
        acc.x += (l0.x + l1.x) * inv; acc.y += (l0.y + l1.y) * inv;
        acc.z += (l0.z + l1.z) * inv; acc.w += (l0.w + l1.w) * inv;
    }
    float4 sv = *(const float4*)(selfp + (size_t)r * 128 + c4);
    float4 bv = *(const float4*)(bias + c4);
    float h0 = fmaxf(acc.x + sv.x + bv.x, 0.f);
    float h1 = fmaxf(acc.y + sv.y + bv.y, 0.f);
    float h2 = fmaxf(acc.z + sv.z + bv.z, 0.f);
    float h3 = fmaxf(acc.w + sv.w + bv.w, 0.f);

    if (!HEADS) {
        *(float4*)(out + (size_t)r * HD + c4) = make_float4(h0, h1, h2, h3);
        return;
    }

    float a12[12];
#pragma unroll
    for (int j = 0; j < 12; j++) {
        float4 w = *(const float4*)(Wh + j * 128 + c4);
        a12[j] = h0 * w.x + h1 * w.y + h2 * w.z + h3 * w.w;
    }
#pragma unroll
    for (int o = 16; o > 0; o >>= 1)
#pragma unroll
        for (int j = 0; j < 12; j++) a12[j] += __shfl_xor_sync(0xffffffffu, a12[j], o);

    if (lane == 0) {
        float tl[5], tp[5], il[4], ip[4];
#pragma unroll
        for (int j = 0; j < 5; j++) { tl[j] = a12[j] + bt[j]; tp[j] = 1.f / (1.f + expf(-tl[j])); }
        float mx = -1e30f;
#pragma unroll
        for (int j = 0; j < 4; j++) { il[j] = a12[5 + j] + bi[j]; mx = fmaxf(mx, il[j]); }
        float se = 0.f;
#pragma unroll
        for (int j = 0; j < 4; j++) { ip[j] = expf(il[j] - mx); se += ip[j]; }
        float inv = 1.f / se;
#pragma unroll
        for (int j = 0; j < 4; j++) ip[j] *= inv;
        float* outT = out;
        float* outI = out + (size_t)NCCOM * 5;
        float* outM = out + (size_t)NCCOM * 9;
#pragma unroll
        for (int j = 0; j < 5; j++) outT[(size_t)r * 5 + j] = tl[j];
#pragma unroll
        for (int j = 0; j < 4; j++) outI[(size_t)r * 4 + j] = il[j];
#pragma unroll
        for (int j = 0; j < 3; j++) {
            float v = a12[9 + j] + bm[j];
#pragma unroll
            for (int t = 0; t < 5; t++) v += tp[t] * __ldg(Wm + (128 + t) * 3 + j);
#pragma unroll
            for (int t = 0; t < 4; t++) v += ip[t] * __ldg(Wm + (133 + t) * 3 + j);
            outM[(size_t)r * 3 + j] = v;
        }
    }
}

// ================= host launcher =================
extern "C" void kernel_launch(void* const* d_in, const int* in_sizes, int n_in,
                              void* d_out, int out_size)
{
    const float* x_c  = (const float*)d_in[0];
    const float* x_t  = (const float*)d_in[1];
    const float* x_cl = (const float*)d_in[2];
    const float* c1sWl = (const float*)d_in[3];
    const float* c1sbl = (const float*)d_in[4];
    const float* c1sWr = (const float*)d_in[5];
    const float* c1aWl = (const float*)d_in[6];
    const float* c1abl = (const float*)d_in[7];
    const float* c1aWr = (const float*)d_in[8];
    const float* c1tWl = (const float*)d_in[9];
    const float* c1tbl = (const float*)d_in[10];
    const float* c1tWr = (const float*)d_in[11];
    const float* c2sWl = (const float*)d_in[12];
    const float* c2sbl = (const float*)d_in[13];
    const float* c2sWr = (const float*)d_in[14];
    const float* c2aWl = (const float*)d_in[15];
    const float* c2abl = (const float*)d_in[16];
    const float* c2aWr = (const float*)d_in[17];
    const float* c2tWl = (const float*)d_in[18];
    const float* c2tbl = (const float*)d_in[19];
    const float* c2tWr = (const float*)d_in[20];
    const float* Wt = (const float*)d_in[21];
    const float* bt = (const float*)d_in[22];
    const float* Wi = (const float*)d_in[23];
    const float* bi = (const float*)d_in[24];
    const float* Wm = (const float*)d_in[25];
    const float* bm = (const float*)d_in[26];
    const int* ei_sim = (const int*)d_in[27];
    const int* ei_ab  = (const int*)d_in[28];
    const int* ei_tg  = (const int*)d_in[29];

    float *y1L, *y1R, *h1, *ytL1, *ytL2, *ycL1, *ycL2;
    int *src, *dst, *deg, *rowptr, *cursor, *csr, *bsum, *boff;
    float *W1, *W2, *Wtc, *Wcc, *Wh, *b1, *b2;
    cudaGetSymbolAddress((void**)&y1L, g_y1L);
    cudaGetSymbolAddress((void**)&y1R, g_y1R);
    cudaGetSymbolAddress((void**)&h1, g_h1);
    cudaGetSymbolAddress((void**)&ytL1, g_ytL1);
    cudaGetSymbolAddress((void**)&ytL2, g_ytL2);
    cudaGetSymbolAddress((void**)&ycL1, g_ycL1);
    cudaGetSymbolAddress((void**)&ycL2, g_ycL2);
    cudaGetSymbolAddress((void**)&src, g_src);
    cudaGetSymbolAddress((void**)&dst, g_dst);
    cudaGetSymbolAddress((void**)&deg, g_deg);
    cudaGetSymbolAddress((void**)&rowptr, g_rowptr);
    cudaGetSymbolAddress((void**)&cursor, g_cursor);
    cudaGetSymbolAddress((void**)&csr, g_csr);
    cudaGetSymbolAddress((void**)&bsum, g_bsum);
    cudaGetSymbolAddress((void**)&boff, g_boff);
    cudaGetSymbolAddress((void**)&W1, g_W1);
    cudaGetSymbolAddress((void**)&W2, g_W2);
    cudaGetSymbolAddress((void**)&Wtc, g_Wtc);
    cudaGetSymbolAddress((void**)&Wcc, g_Wcc);
    cudaGetSymbolAddress((void**)&Wh, g_Wh);
    cudaGetSymbolAddress((void**)&b1, g_b1);
    cudaGetSymbolAddress((void**)&b2, g_b2);

    int* srcS = src;              int* dstS = dst;
    int* srcA = src + ESIM;       int* dstA = dst + ESIM;
    int* srcT = src + ESIM + EAB; int* dstT = dst + ESIM + EAB;

    // Launch order arranged so the big GEMM is the 6th launch (ncu -s 5 -c 1).
    detect_kernel<<<1, 1>>>(ei_sim);                                    // 1
    zero_kernel<<<512, 256>>>((float*)deg, NROWS3 / 4);                 // 2
    build_weights<<<(165632 + 255) / 256, 256>>>(                        // 3
        c1sWl, c1sWr, c1aWr, c1tWr, c2sWl, c2sWr, c2aWr, c2tWr,
        c1aWl, c2aWl, c1tWl, c2tWl, c1sbl, c1abl, c1tbl, c2sbl, c2abl, c2tbl,
        Wt, Wi, Wm);
    convert_count<<<(ESIM + 255) / 256, 256>>>(ei_sim, srcS, dstS, deg, ESIM, 0);        // 4
    convert_count<<<(EAB + 255) / 256, 256>>>(ei_ab, srcA, dstA, deg, EAB, NCCOM);       // 5
    gemm_x2<256><<<dim3((NCCOM + 127) / 128, 2), 256>>>(x_c, W1, y1L, y1R, NCCOM);       // 6 <- ncu
    convert_count<<<(ETG + 255) / 256, 256>>>(ei_tg, srcT, dstT, deg, ETG, 2 * NCCOM);   // 7

    // CSR build
    scan_bsum<<<SCAN_NB, SCAN_B>>>(deg, bsum, NROWS3);
    scan_offsets<<<1, 1>>>(bsum, boff, SCAN_NB);
    scan_write<<<SCAN_NB, SCAN_B>>>(deg, boff, rowptr, cursor, NROWS3);
    fill_csr<<<(ESIM + 255) / 256, 256>>>(srcS, dstS, cursor, csr, ESIM, 0);
    fill_csr<<<(EAB + 255) / 256, 256>>>(srcA, dstA, cursor, csr, EAB, NCCOM);
    fill_csr<<<(ETG + 255) / 256, 256>>>(srcT, dstT, cursor, csr, ETG, 2 * NCCOM);

    // small GEMMs (topic/claim, both layers at once)
    gemm_x2<128><<<dim3((NTOP + 127) / 128, 2), 256>>>(x_t, Wtc, ytL1, ytL2, NTOP);
    gemm_x2<128><<<dim3((NCLM + 127) / 128, 2), 256>>>(x_cl, Wcc, ycL1, ycL2, NCLM);

    // layer-1 gather + combine
    gather_kernel<false><<<(NCCOM * 32 + 255) / 256, 256>>>(
        y1L, ytL1, ycL1, rowptr, csr, y1R, b1, h1,
        nullptr, nullptr, nullptr, nullptr, nullptr);

    // layer-2 GEMM (reuses y1L/y1R buffers) + gather + fused heads
    gemm_x2<128><<<dim3((NCCOM + 127) / 128, 2), 256>>>(h1, W2, y1L, y1R, NCCOM);
    gather_kernel<true><<<(NCCOM * 32 + 255) / 256, 256>>>(
        y1L, ytL2, ycL2, rowptr, csr, y1R, b2, (float*)d_out,
        Wh, Wm, bt, bi, bm);
}